// round 13
// baseline (speedup 1.0000x reference)
#include <cuda_runtime.h>
#include <cuda_pipeline.h>

#define LSEQ 32768
#define T 14
#define EMB 300
#define CHUNKS 512
#define CB 64             // chunk length (CHUNKS*CB == LSEQ)
#define SUPER 32          // supernodes per side
#define SCH 16            // chunks per supernode
#define START_TAG 12
#define STOP_TAG 13
#define NEGV (-10000.0f)
#define NINF (-1e30f)

#define FB 32             // positions per feats block
#define FST 8             // positions per stage

// ---------------- scratch (static device globals; no allocation) -------------
__device__ float g_featsP[LSEQ * 16];          // raw feats padded to 16
__device__ float g_goldpart[1024];
__device__ float g_Em[CHUNKS * 224];           // fwd chunk mats (linear, row-norm)
__device__ float g_m[CHUNKS * 16];             // row log-offsets
__device__ float g_Cv[CHUNKS * 224];           // viterbi chunk mats
__device__ float g_SEm[SUPER * 224];
__device__ float g_Sm[SUPER * 16];
__device__ float g_SCv[SUPER * 224];
__device__ float g_vsuper[SUPER * 16];
__device__ int   g_best_last;
__device__ __align__(16) unsigned char g_F[CHUNKS * T];
__device__ int   g_carry[CHUNKS];
// counters: g_cnt_sup reset by k_tail bid512; g_cnt_bp/g_flag by k_feats
__device__ int   g_cnt_sup;
__device__ int   g_cnt_bp;
__device__ int   g_flag;

__device__ __forceinline__ void ld14(const float* p, float* u) {
    const float4* q = (const float4*)p;
    float4 a = q[0], b = q[1], c = q[2], d = q[3];
    u[0]=a.x; u[1]=a.y; u[2]=a.z; u[3]=a.w;
    u[4]=b.x; u[5]=b.y; u[6]=b.z; u[7]=b.w;
    u[8]=c.x; u[9]=c.y; u[10]=c.z; u[11]=c.w;
    u[12]=d.x; u[13]=d.y;
}
__device__ __forceinline__ float max14(const float* u) {
    float a0=fmaxf(u[0],u[1]), a1=fmaxf(u[2],u[3]), a2=fmaxf(u[4],u[5]);
    float a3=fmaxf(u[6],u[7]), a4=fmaxf(u[8],u[9]), a5=fmaxf(u[10],u[11]);
    float a6=fmaxf(u[12],u[13]);
    float b0=fmaxf(a0,a1), b1=fmaxf(a2,a3), b2=fmaxf(a4,a5);
    return fmaxf(fmaxf(b0,b1), fmaxf(b2,a6));
}
// first-max argmax via exact-equality mask (FMNMX returns an input bitwise)
__device__ __forceinline__ int argfirst14(const float* a, float best) {
    unsigned m = 0;
#pragma unroll
    for (int p = 0; p < T; p++) m |= (a[p] == best) ? (1u << p) : 0u;
    return __ffs(m) - 1;
}

// ================= K1: feats + gold — cp.async staged (1024 x 128) ===========
__global__ void __launch_bounds__(128) k_feats(
        const int* __restrict__ sent, const int* __restrict__ tags,
        const float* __restrict__ emb, const float* __restrict__ W,
        const float* __restrict__ trans) {
    __shared__ __align__(16) float Ws[T * EMB];
    __shared__ __align__(16) float rows[2][FST][304];   // 304-pad rows
    __shared__ int   sids[FB];
    __shared__ float red[128];
    int bid = blockIdx.x, tid = threadIdx.x;
    if (bid == 0 && tid == 0) { g_cnt_bp = 0; g_flag = 0; }   // resets for K4
    int pbase = bid * FB;
    if (tid < FB) sids[tid] = __ldg(sent + pbase + tid);
    {   const float4* src = (const float4*)W;
        float4* dst = (float4*)Ws;
        for (int i = tid; i < (T * EMB) / 4; i += 128) dst[i] = src[i]; }
    __syncthreads();

#define COPY_STAGE(ss, bb) do {                                              \
    for (int idx = tid; idx < FST * 75; idx += 128) {                        \
        int rr = idx / 75, cc = idx % 75;                                    \
        const float* srcp = emb + (size_t)sids[(ss) * FST + rr] * EMB + cc*4;\
        __pipeline_memcpy_async(&rows[bb][rr][cc * 4], srcp, 16);            \
    }                                                                        \
    __pipeline_commit();                                                     \
} while (0)

    int buf = 0;
    COPY_STAGE(0, 0);
    float gsum = 0.0f;
    const int pis = tid >> 4;       // position-in-stage 0..7
    const int j = tid & 15;         // 16th-of-EMB
    const int nb = (j < 11) ? 5 : 4;
    for (int s = 0; s < FB / FST; s++) {
        if (s + 1 < FB / FST) COPY_STAGE(s + 1, buf ^ 1);
        if (s + 1 < FB / FST) __pipeline_wait_prior(1);
        else                  __pipeline_wait_prior(0);
        __syncthreads();
        const float* erow = rows[buf][pis];
        float4 ev[5];
#pragma unroll
        for (int i = 0; i < 5; i++)
            if (i < nb) ev[i] = *(const float4*)(erow + (j + 16 * i) * 4);
        float acc[T];
#pragma unroll
        for (int t = 0; t < T; t++) acc[t] = 0.0f;
#pragma unroll
        for (int t = 0; t < T; t++) {
#pragma unroll
            for (int i = 0; i < 5; i++) if (i < nb) {
                float4 wv = ((const float4*)Ws)[t * 75 + j + 16 * i];
                float a = acc[t];
                a = fmaf(ev[i].x, wv.x, a); a = fmaf(ev[i].y, wv.y, a);
                a = fmaf(ev[i].z, wv.z, a); a = fmaf(ev[i].w, wv.w, a);
                acc[t] = a;
            }
        }
#pragma unroll
        for (int t = 0; t < T; t++) {
            acc[t] += __shfl_xor_sync(0xFFFFFFFFu, acc[t], 1, 16);
            acc[t] += __shfl_xor_sync(0xFFFFFFFFu, acc[t], 2, 16);
            acc[t] += __shfl_xor_sync(0xFFFFFFFFu, acc[t], 4, 16);
            acc[t] += __shfl_xor_sync(0xFFFFFFFFu, acc[t], 8, 16);
        }
        int pos = pbase + s * FST + pis;
        if (j < 4) {
            float4 st;
            st.x = (j==0)?acc[0]:(j==1)?acc[4]:(j==2)?acc[8]:acc[12];
            st.y = (j==0)?acc[1]:(j==1)?acc[5]:(j==2)?acc[9]:acc[13];
            st.z = (j==0)?acc[2]:(j==1)?acc[6]:(j==2)?acc[10]:0.0f;
            st.w = (j==0)?acc[3]:(j==1)?acc[7]:(j==2)?acc[11]:0.0f;
            ((float4*)(g_featsP + pos * 16))[j] = st;
        }
        if (j == 0) {
            int tg = __ldg(tags + pos);
            int prev = (pos == 0) ? START_TAG : __ldg(tags + pos - 1);
            float emit = 0.0f;
#pragma unroll
            for (int t = 0; t < T; t++) if (t == tg) emit = acc[t];
            float gv = trans[tg * T + prev] + emit;
            if (pos == LSEQ - 1) gv += trans[STOP_TAG * T + tg];
            gsum += gv;
        }
        __syncthreads();
        buf ^= 1;
    }
    red[tid] = gsum;
    __syncthreads();
    for (int off = 64; off; off >>= 1) {
        if (tid < off) red[tid] += red[tid + off];
        __syncthreads();
    }
    if (tid == 0) g_goldpart[bid] = red[0];
#undef COPY_STAGE
}

// ================= K2: chunk recurrences (1024 blocks x 224 thr) =============
__global__ void __launch_bounds__(224, 6) k_chunks(const float* __restrict__ trans) {
    __shared__ struct {
        alignas(16) float aux[CB * 16];
        alignas(16) float U[2][256];
        alignas(16) float Trs[256];
        alignas(16) float Msm[256];
        alignas(16) float fmaxs[CB];
        float fsum;
    } s;
    int bid = blockIdx.x, tid = threadIdx.x;
    int fwd = (bid >= CHUNKS);
    int chunk = fwd ? bid - CHUNKS : bid;
    {   const float4* src = (const float4*)(g_featsP + chunk * CB * 16);
        float4* dst = (float4*)s.aux;
        for (int i = tid; i < CB * 4; i += 224) dst[i] = src[i]; }
    if (tid < 196) s.Trs[(tid / 14) * 16 + (tid % 14)] =
        fwd ? __expf(trans[tid]) : trans[tid];
    __syncthreads();
    if (fwd) {
        if (tid < CB) {
            float f[T]; ld14(s.aux + tid * 16, f);
            float fm = max14(f);
            s.fmaxs[tid] = fm;
#pragma unroll
            for (int jj = 0; jj < T; jj++) s.aux[tid * 16 + jj] = __expf(f[jj] - fm);
        }
        __syncthreads();
        if (tid < 32) {
            float ff = s.fmaxs[tid] + s.fmaxs[tid + 32];
#pragma unroll
            for (int d = 16; d; d >>= 1) ff += __shfl_xor_sync(0xFFFFFFFFu, ff, d);
            if (tid == 0) s.fsum = ff;
        }
        __syncthreads();
    }
    int warp = tid >> 5, lane = tid & 31;
    int col = 2 * warp + (lane >> 4), lg = lane & 15;
    bool ract = (lg < 14);
    float tr[T]; ld14(&s.Trs[lg * 16], tr);
    if (!fwd) {
        if (ract) s.U[0][col * 16 + lg] = (lg == col) ? 0.0f : NINF;
        __syncwarp();
        int b = 0; float vfin = NINF;
        for (int l = 0; l < CB; l++) {
            float u[T]; ld14(&s.U[b][col * 16], u);
            float a[T];
#pragma unroll
            for (int p = 0; p < T; p++) a[p] = u[p] + tr[p];
            vfin = max14(a) + s.aux[l * 16 + lg];
            if (ract) s.U[b ^ 1][col * 16 + lg] = vfin;
            __syncwarp(); b ^= 1;
        }
        if (ract) g_Cv[chunk * 224 + lg * 16 + col] = vfin;
    } else {
        if (ract) s.U[0][col * 16 + lg] = (lg == col) ? 1.0f : 0.0f;
        __syncwarp();
        int b = 0; float ffin = 0.0f, ofs = 0.0f;
        for (int l4 = 0; l4 < CB; l4 += 4) {
            {   float u[T]; ld14(&s.U[b][col * 16], u);
                float cm = fmaxf(max14(u), 1e-35f);
                float inv = __fdividef(1.0f, cm);
                ofs += __logf(cm);
                float s0 = 0.0f, s1 = 0.0f;
#pragma unroll
                for (int p = 0; p < 7; p++) s0 = fmaf(tr[p], u[p], s0);
#pragma unroll
                for (int p = 7; p < T; p++) s1 = fmaf(tr[p], u[p], s1);
                ffin = (s0 + s1) * inv * s.aux[l4 * 16 + lg];
                if (ract) s.U[b ^ 1][col * 16 + lg] = ffin;
                __syncwarp(); b ^= 1;
            }
#pragma unroll
            for (int ll = 1; ll < 4; ll++) {
                float u[T]; ld14(&s.U[b][col * 16], u);
                float s0 = 0.0f, s1 = 0.0f;
#pragma unroll
                for (int p = 0; p < 7; p++) s0 = fmaf(tr[p], u[p], s0);
#pragma unroll
                for (int p = 7; p < T; p++) s1 = fmaf(tr[p], u[p], s1);
                ffin = (s0 + s1) * s.aux[(l4 + ll) * 16 + lg];
                if (ract) s.U[b ^ 1][col * 16 + lg] = ffin;
                __syncwarp(); b ^= 1;
            }
        }
        float Cf = NINF;
        if (ract) {
            Cf = (ffin > 0.0f) ? __logf(ffin) + ofs + s.fsum : NINF;
            s.Msm[lg * 16 + col] = Cf;
        }
        __syncthreads();
        if (ract) {
            float r[T]; ld14(&s.Msm[lg * 16], r);
            float rm = max14(r);
            g_Em[chunk * 224 + lg * 16 + col] = __expf(Cf - rm);
            if (col == 0) g_m[chunk * 16 + lg] = rm;
        }
    }
}

// ================= K3: supers (smem-preloaded) + vit scan ====================
__global__ void __launch_bounds__(224) k_sup(void) {
    struct SupS {
        alignas(16) float A[16 * 224];
        alignas(16) float m[256];
        alignas(16) float U[2][256];
        alignas(16) float Msm[256];
    };
    struct ScanS { alignas(16) float B[32 * 224 + 32]; };
    __shared__ union { SupS s; ScanS sc; } u_;
    int bid = blockIdx.x, tid = threadIdx.x;
    if (bid < 32) {
        {   const float4* src = (const float4*)(g_Cv + bid * 3584);
            float4* dst = (float4*)u_.s.A;
            for (int i = tid; i < 896; i += 224) dst[i] = src[i]; }
        int n = tid % 14, c = tid / 14;
        u_.s.U[0][c * 16 + n] = (n == c) ? 0.0f : NINF;
        __syncthreads();
        int b = 0; float val = NINF;
        for (int k = 0; k < SCH; k++) {
            float row[T]; ld14(&u_.s.A[k * 224 + n * 16], row);
            float uc[T]; ld14(&u_.s.U[b][c * 16], uc);
            float a[T];
#pragma unroll
            for (int p = 0; p < T; p++) a[p] = row[p] + uc[p];
            val = max14(a);
            u_.s.U[b ^ 1][c * 16 + n] = val;
            __syncthreads(); b ^= 1;
        }
        if (c < 14) g_SCv[bid * 224 + n * 16 + c] = val;
        __threadfence(); __syncthreads();
        if (tid == 0) atomicAdd(&g_cnt_sup, 1);
    } else if (bid < 64) {
        int g = bid - 32;
        {   const float4* src = (const float4*)(g_Em + g * 3584);
            float4* dst = (float4*)u_.s.A;
            for (int i = tid; i < 896; i += 224) dst[i] = src[i]; }
        {   const float4* src = (const float4*)(g_m + g * 256);
            float4* dst = (float4*)u_.s.m;
            for (int i = tid; i < 64; i += 224) dst[i] = src[i]; }
        int n = tid % 14, c = tid / 14;
        u_.s.U[0][c * 16 + n] = (n == c) ? 1.0f : 0.0f;
        __syncthreads();
        int b = 0; float val = 0.0f, o2 = 0.0f;
        for (int k = 0; k < SCH; k++) {
            float row[T]; ld14(&u_.s.A[k * 224 + n * 16], row);
            float uc[T]; ld14(&u_.s.U[b][c * 16], uc);
            float mk = u_.s.m[k * 16 + n];
            float s0 = 0.0f, s1 = 0.0f;
#pragma unroll
            for (int p = 0; p < 7; p++) s0 = fmaf(row[p], uc[p], s0);
#pragma unroll
            for (int p = 7; p < T; p++) s1 = fmaf(row[p], uc[p], s1);
            float tlog = mk + __logf(fmaxf(s0 + s1, 1e-38f));
            u_.s.Msm[c * 16 + n] = tlog;
            __syncthreads();
            float tc[T]; ld14(&u_.s.Msm[c * 16], tc);
            float cmax = max14(tc);
            val = __expf(tlog - cmax);
            u_.s.U[b ^ 1][c * 16 + n] = val;
            o2 += cmax;
            __syncthreads(); b ^= 1;
        }
        float Sl = (val > 0.0f) ? __logf(val) + o2 : NINF;
        u_.s.Msm[n * 16 + c] = Sl;
        __syncthreads();
        if (c < 14) {
            float r[T]; ld14(&u_.s.Msm[n * 16], r);
            float rm = max14(r);
            g_SEm[g * 224 + n * 16 + c] = __expf(Sl - rm);
            if (c == 0) g_Sm[g * 16 + n] = rm;
        }
    } else {
        if (tid == 0) { while (atomicAdd(&g_cnt_sup, 0) < 32) __nanosleep(64); }
        __syncthreads(); __threadfence();
        {   const float4* src = (const float4*)g_SCv;
            float4* dst = (float4*)u_.sc.B;
            for (int i = tid; i < 1792; i += 224) dst[i] = __ldcg(src + i); }
        __syncthreads();
        if (tid < 16) {
            const unsigned M16 = 0xFFFFu;
            int ln = tid;
            float v = (ln == START_TAG) ? 0.0f : NEGV;
            for (int i = 0; i < SUPER; i++) {
                g_vsuper[i * 16 + ln] = (ln < T) ? v : NEGV;
                float row[T]; ld14(&u_.sc.B[i * 224 + ln * 16], row);
                float nv = -3e38f;
#pragma unroll
                for (int p = 0; p < T; p++) {
                    float vp = __shfl_sync(M16, v, p, 16);
                    nv = fmaxf(nv, row[p] + vp);
                }
                v = (ln < T) ? nv : NEGV;
            }
        }
    }
}

// ================= K4: tail (quartered) + fwd scan block (513 x 256) =========
__global__ void __launch_bounds__(256) k_tail(const float* __restrict__ trans,
                                              float* __restrict__ out) {
    struct TailS {
        alignas(16) float raw[CB * 16];
        alignas(16) float fix[15 * 224 + 4];
        alignas(16) float vs[16];
        alignas(16) float term[16];
        alignas(16) unsigned char bp[CB * T];
        alignas(16) unsigned char Fs[CHUNKS * T];
        alignas(16) unsigned char Q[4][16];
        alignas(16) unsigned char comp[16 * T];
        int sgrp[17];
        int role;
    };
    struct FscanS {
        alignas(16) float B[32 * 224 + 32];
        alignas(16) float m[SUPER * 16 + 16];
        alignas(16) float gold[1024];
    };
    __shared__ union { TailS t; FscanS f; } u_;
    int bid = blockIdx.x, tid = threadIdx.x;

    if (bid == 512) {
        // ---- forward scan + nll (hides under the 512 tail blocks) ----
        if (tid == 0) g_cnt_sup = 0;                 // reset for next replay
        {   const float4* src = (const float4*)g_SEm;
            float4* dst = (float4*)u_.f.B;
            for (int i = tid; i < 1792; i += 256) dst[i] = src[i]; }
        {   const float4* src = (const float4*)g_Sm;
            float4* dst = (float4*)u_.f.m;
            for (int i = tid; i < 128; i += 256) dst[i] = src[i]; }
        {   const float4* src = (const float4*)g_goldpart;
            float4* dst = (float4*)u_.f.gold;
            for (int i = tid; i < 256; i += 256) dst[i] = src[i]; }
        __syncthreads();
        if (tid < 16) {
            const unsigned M16 = 0xFFFFu;
            int ln = tid;
            float u = (ln == START_TAG) ? 1.0f : 0.0f;
            float O = 0.0f;
            for (int i = 0; i < SUPER; i++) {
                float row[T]; float mk;
                if (ln < T) { ld14(&u_.f.B[i * 224 + ln * 16], row);
                              mk = u_.f.m[i * 16 + ln]; }
                else {
#pragma unroll
                    for (int p = 0; p < T; p++) row[p] = 0.0f;
                    mk = -3e38f;
                }
                float w = 0.0f;
#pragma unroll
                for (int p = 0; p < T; p++) {
                    float up = __shfl_sync(M16, u, p, 16);
                    w = fmaf(row[p], up, w);
                }
                float t2 = mk + __logf(fmaxf(w, 1e-38f));
                float M = t2;
#pragma unroll
                for (int d = 8; d; d >>= 1) M = fmaxf(M, __shfl_xor_sync(M16, M, d, 16));
                u = __expf(t2 - M);
                O += M;
            }
            float val = (ln < T) ? (((u > 0.0f) ? __logf(u) : NINF) + O +
                                    trans[STOP_TAG * T + ln])
                                 : -3e38f;
            float M2 = val;
#pragma unroll
            for (int d = 8; d; d >>= 1) M2 = fmaxf(M2, __shfl_xor_sync(M16, M2, d, 16));
            float e = __expf(val - M2);
#pragma unroll
            for (int d = 8; d; d >>= 1) e += __shfl_xor_sync(M16, e, d, 16);
            float fwd_score = M2 + __logf(e);
            float gp = 0.0f;
            for (int jj = ln; jj < 1024; jj += 16) gp += u_.f.gold[jj];
#pragma unroll
            for (int d = 8; d; d >>= 1) gp += __shfl_xor_sync(M16, gp, d, 16);
            if (ln == 0) out[0] = fwd_score - gp;    // nll
        }
        return;
    }

    // ---- tail role ----
    int chunk = bid;
    int sup = chunk >> 4, base = sup << 4, r = chunk - base;
    {   const float4* src = (const float4*)(g_featsP + chunk * CB * 16);
        float4* dst = (float4*)u_.t.raw;
        for (int i = tid; i < CB * 4; i += 256) dst[i] = src[i]; }
    if (r > 0) {
        const float4* src = (const float4*)(g_Cv + base * 224);
        float4* dst = (float4*)u_.t.fix;
        for (int i = tid; i < r * 56; i += 256) dst[i] = src[i];
    }
    if (tid < 4) ((float4*)u_.t.vs)[tid] = ((const float4*)(g_vsuper + sup * 16))[tid];
    __syncthreads();
    if (tid < T) {
        int ln = tid;
        float v = u_.t.vs[ln];
        for (int k = 0; k < r; k++) {
            float row[T]; ld14(&u_.t.fix[k * 224 + ln * 16], row);
            float fvall[T];
#pragma unroll
            for (int p = 0; p < T; p++) fvall[p] = __shfl_sync(0x3FFFu, v, p);
            float nv = NINF;
#pragma unroll
            for (int p = 0; p < T; p++) nv = fmaxf(nv, row[p] + fvall[p]);
            v = nv;
        }
        float tr[T];
#pragma unroll
        for (int p = 0; p < T; p++) tr[p] = trans[ln * T + p];
        float fv = v;
        for (int l = 0; l < CB; l++) {
            float fvall[T];
#pragma unroll
            for (int p = 0; p < T; p++) fvall[p] = __shfl_sync(0x3FFFu, fv, p);
            float a[T];
#pragma unroll
            for (int p = 0; p < T; p++) a[p] = fvall[p] + tr[p];
            float best = max14(a);                    // critical path: FMNMX only
            fv = best + u_.t.raw[l * 16 + ln];
            u_.t.bp[l * T + ln] = (unsigned char)argfirst14(a, best);  // off-path
        }
        if (chunk == CHUNKS - 1) u_.t.term[ln] = fv + trans[STOP_TAG * T + ln];
    }
    __syncthreads();
    // quarter backtrace maps (4 x 14 threads, 16 steps each)
    if (tid < 56) {
        int q = tid / 14, x = tid % 14;
        int t = x;
        for (int l = q * 16 + 15; l >= q * 16; l--) t = u_.t.bp[l * T + t];
        u_.t.Q[q][x] = (unsigned char)t;
    }
    __syncthreads();
    if (tid < T) {
        int x = tid;
        g_F[chunk * T + x] = u_.t.Q[0][u_.t.Q[1][u_.t.Q[2][u_.t.Q[3][x]]]];
    }
    if (chunk == CHUNKS - 1 && tid == 0) {
        float a2[T];
#pragma unroll
        for (int p = 0; p < T; p++) a2[p] = u_.t.term[p];
        float best = max14(a2);
        g_best_last = argfirst14(a2, best);
        out[1] = best;                                 // path_score
    }
    __threadfence(); __syncthreads();
    if (tid == 0) {
        int old = atomicAdd(&g_cnt_bp, 1);
        u_.t.role = (old == CHUNKS - 1);
    }
    __syncthreads();
    if (u_.t.role) {
        // ---- carry (last-done block): 16 groups of 32 chunks ----
        __threadfence();
        {   const int4* src = (const int4*)g_F;
            int4* dst = (int4*)u_.t.Fs;
            for (int i = tid; i < (CHUNKS * T) / 16; i += 256) dst[i] = __ldcg(src + i); }
        __syncthreads();
        if (tid < 16 * T) {
            int g = tid / T, x = tid % T;
            int t = x;
            for (int l = g * 32 + 31; l >= g * 32; l--) t = u_.t.Fs[l * T + t];
            u_.t.comp[g * T + x] = (unsigned char)t;
        }
        __syncthreads();
        if (tid == 0) {
            int sgv = g_best_last;
            u_.t.sgrp[16] = sgv;
            for (int g = 15; g >= 0; g--) { sgv = u_.t.comp[g * T + sgv]; u_.t.sgrp[g] = sgv; }
        }
        __syncthreads();
        if (tid < 16) {
            int g = tid;
            int t = u_.t.sgrp[g + 1];
            for (int l = g * 32 + 31; l >= g * 32; l--) {
                g_carry[l] = t;
                t = u_.t.Fs[l * T + t];
            }
        }
        __threadfence(); __syncthreads();
        if (tid == 0) atomicExch(&g_flag, 1);
    } else {
        if (tid == 0) { while (atomicAdd(&g_flag, 0) == 0) __nanosleep(128); }
        __syncthreads();
    }
    __threadfence();
    // ---- emit: 4 parallel 16-step quarter walks ----
    if (tid < 4) {
        int q = tid;
        int s3 = g_carry[chunk];
        int s2 = u_.t.Q[3][s3];
        int s1 = u_.t.Q[2][s2];
        int s0 = u_.t.Q[1][s1];
        int st = (q == 3) ? s3 : (q == 2) ? s2 : (q == 1) ? s1 : s0;
        for (int l = q * 16 + 15; l >= q * 16; l--) {
            out[2 + chunk * CB + l] = (float)st;
            st = u_.t.bp[l * T + st];
        }
    }
}

// ---------------- launch -----------------------------------------------------
extern "C" void kernel_launch(void* const* d_in, const int* in_sizes, int n_in,
                              void* d_out, int out_size) {
    const int*   sent  = (const int*)d_in[0];
    const int*   tags  = (const int*)d_in[1];
    const float* emb   = (const float*)d_in[2];
    const float* W     = (const float*)d_in[3];
    const float* trans = (const float*)d_in[4];
    float* out = (float*)d_out;
    (void)in_sizes; (void)n_in; (void)out_size;

    k_feats<<<1024, 128>>>(sent, tags, emb, W, trans);
    k_chunks<<<2 * CHUNKS, 224>>>(trans);
    k_sup<<<65, 224>>>();
    k_tail<<<CHUNKS + 1, 256>>>(trans, out);
}

// round 14
// speedup vs baseline: 1.1690x; 1.1690x over previous
#include <cuda_runtime.h>

#define LSEQ 32768
#define T 14
#define EMB 300
#define CHUNKS 512
#define CB 64             // chunk length (CHUNKS*CB == LSEQ)
#define SUPER 32          // supernodes per side
#define SCH 16            // chunks per supernode
#define START_TAG 12
#define STOP_TAG 13
#define NEGV (-10000.0f)
#define NINF (-1e30f)

// ---------------- scratch (static device globals; no allocation) -------------
__device__ float g_featsP[LSEQ * 16];          // raw feats padded to 16
__device__ float g_goldpart[512];
__device__ float g_Em[CHUNKS * 224];           // fwd chunk mats (linear, row-norm)
__device__ float g_m[CHUNKS * 16];             // row log-offsets
__device__ float g_Cv[CHUNKS * 224];           // viterbi chunk mats
__device__ float g_SEm[SUPER * 224];
__device__ float g_Sm[SUPER * 16];
__device__ float g_SCv[SUPER * 224];
__device__ float g_vsuper[SUPER * 16];
__device__ int   g_best_last;
__device__ __align__(16) unsigned char g_F[CHUNKS * T];
__device__ int   g_carry[CHUNKS];
// counters: g_cnt_sup reset by k_tail bid512; g_cnt_bp/g_flag by k_feats
__device__ int   g_cnt_sup;
__device__ int   g_cnt_bp;
__device__ int   g_flag;

__device__ __forceinline__ void ld14(const float* p, float* u) {
    const float4* q = (const float4*)p;
    float4 a = q[0], b = q[1], c = q[2], d = q[3];
    u[0]=a.x; u[1]=a.y; u[2]=a.z; u[3]=a.w;
    u[4]=b.x; u[5]=b.y; u[6]=b.z; u[7]=b.w;
    u[8]=c.x; u[9]=c.y; u[10]=c.z; u[11]=c.w;
    u[12]=d.x; u[13]=d.y;
}
__device__ __forceinline__ float max14(const float* u) {
    float a0=fmaxf(u[0],u[1]), a1=fmaxf(u[2],u[3]), a2=fmaxf(u[4],u[5]);
    float a3=fmaxf(u[6],u[7]), a4=fmaxf(u[8],u[9]), a5=fmaxf(u[10],u[11]);
    float a6=fmaxf(u[12],u[13]);
    float b0=fmaxf(a0,a1), b1=fmaxf(a2,a3), b2=fmaxf(a4,a5);
    return fmaxf(fmaxf(b0,b1), fmaxf(b2,a6));
}
// first-max argmax via exact-equality mask (FMNMX returns an input bitwise)
__device__ __forceinline__ int argfirst14(const float* a, float best) {
    unsigned m = 0;
#pragma unroll
    for (int p = 0; p < T; p++) m |= (a[p] == best) ? (1u << p) : 0u;
    return __ffs(m) - 1;
}

// ================= K1: feats + gold (512 x 128; 2 positions / thread) ========
__global__ void __launch_bounds__(128) k_feats(
        const int* __restrict__ sent, const int* __restrict__ tags,
        const float* __restrict__ emb, const float* __restrict__ W,
        const float* __restrict__ trans) {
    __shared__ __align__(16) float Ws[T * EMB];
    __shared__ float red[128];
    int bid = blockIdx.x, tid = threadIdx.x;
    if (bid == 0 && tid == 0) { g_cnt_bp = 0; g_flag = 0; }   // resets for K4
    {   const float4* src = (const float4*)W;
        float4* dst = (float4*)Ws;
        for (int i = tid; i < (T * EMB) / 4; i += 128) dst[i] = src[i]; }
    __syncthreads();
    int pairL = tid >> 2, q = tid & 3;
    int pos0 = bid * 64 + pairL * 2;
    int pos1 = pos0 + 1;
    const float4* e0 = (const float4*)(emb + (size_t)__ldg(sent + pos0) * EMB);
    const float4* e1 = (const float4*)(emb + (size_t)__ldg(sent + pos1) * EMB);
    float acc0[T], acc1[T];
#pragma unroll
    for (int t = 0; t < T; t++) { acc0[t] = 0.0f; acc1[t] = 0.0f; }
#pragma unroll
    for (int j = 0; j < 19; j++) {
        int k = 4 * j + q;
        if (k < 75) {
            float4 ev0 = __ldg(e0 + k);
            float4 ev1 = __ldg(e1 + k);
#pragma unroll
            for (int t = 0; t < T; t++) {
                float4 wv = *(const float4*)(Ws + t * EMB + 4 * k);
                float a0 = acc0[t], a1 = acc1[t];
                a0 = fmaf(ev0.x, wv.x, a0); a1 = fmaf(ev1.x, wv.x, a1);
                a0 = fmaf(ev0.y, wv.y, a0); a1 = fmaf(ev1.y, wv.y, a1);
                a0 = fmaf(ev0.z, wv.z, a0); a1 = fmaf(ev1.z, wv.z, a1);
                a0 = fmaf(ev0.w, wv.w, a0); a1 = fmaf(ev1.w, wv.w, a1);
                acc0[t] = a0; acc1[t] = a1;
            }
        }
    }
#pragma unroll
    for (int t = 0; t < T; t++) {
        acc0[t] += __shfl_xor_sync(0xFFFFFFFFu, acc0[t], 1, 4);
        acc0[t] += __shfl_xor_sync(0xFFFFFFFFu, acc0[t], 2, 4);
        acc1[t] += __shfl_xor_sync(0xFFFFFFFFu, acc1[t], 1, 4);
        acc1[t] += __shfl_xor_sync(0xFFFFFFFFu, acc1[t], 2, 4);
    }
    {   float4 st;
        st.x = (q==0)?acc0[0]:(q==1)?acc0[4]:(q==2)?acc0[8]:acc0[12];
        st.y = (q==0)?acc0[1]:(q==1)?acc0[5]:(q==2)?acc0[9]:acc0[13];
        st.z = (q==0)?acc0[2]:(q==1)?acc0[6]:(q==2)?acc0[10]:0.0f;
        st.w = (q==0)?acc0[3]:(q==1)?acc0[7]:(q==2)?acc0[11]:0.0f;
        ((float4*)(g_featsP + pos0 * 16))[q] = st;
        st.x = (q==0)?acc1[0]:(q==1)?acc1[4]:(q==2)?acc1[8]:acc1[12];
        st.y = (q==0)?acc1[1]:(q==1)?acc1[5]:(q==2)?acc1[9]:acc1[13];
        st.z = (q==0)?acc1[2]:(q==1)?acc1[6]:(q==2)?acc1[10]:0.0f;
        st.w = (q==0)?acc1[3]:(q==1)?acc1[7]:(q==2)?acc1[11]:0.0f;
        ((float4*)(g_featsP + pos1 * 16))[q] = st;
    }
    float gv = 0.0f;
    if (q == 0) {
        int tg0 = __ldg(tags + pos0);
        int prev0 = (pos0 == 0) ? START_TAG : __ldg(tags + pos0 - 1);
        float emit0 = 0.0f;
#pragma unroll
        for (int t = 0; t < T; t++) if (t == tg0) emit0 = acc0[t];
        gv = trans[tg0 * T + prev0] + emit0;
        int tg1 = __ldg(tags + pos1);
        float emit1 = 0.0f;
#pragma unroll
        for (int t = 0; t < T; t++) if (t == tg1) emit1 = acc1[t];
        gv += trans[tg1 * T + tg0] + emit1;
        if (pos1 == LSEQ - 1) gv += trans[STOP_TAG * T + tg1];
    }
    red[tid] = gv;
    __syncthreads();
    for (int off = 64; off; off >>= 1) {
        if (tid < off) red[tid] += red[tid + off];
        __syncthreads();
    }
    if (tid == 0) g_goldpart[bid] = red[0];
}

// ================= K2: chunk recurrences (1024 blocks x 224 thr) =============
__global__ void __launch_bounds__(224, 6) k_chunks(const float* __restrict__ trans) {
    __shared__ struct {
        alignas(16) float aux[CB * 16];
        alignas(16) float U[2][256];
        alignas(16) float Trs[256];
        alignas(16) float Msm[256];
        alignas(16) float fmaxs[CB];
        float fsum;
    } s;
    int bid = blockIdx.x, tid = threadIdx.x;
    int fwd = (bid >= CHUNKS);
    int chunk = fwd ? bid - CHUNKS : bid;
    {   const float4* src = (const float4*)(g_featsP + chunk * CB * 16);
        float4* dst = (float4*)s.aux;
        for (int i = tid; i < CB * 4; i += 224) dst[i] = src[i]; }
    if (tid < 196) s.Trs[(tid / 14) * 16 + (tid % 14)] =
        fwd ? __expf(trans[tid]) : trans[tid];
    __syncthreads();
    if (fwd) {
        if (tid < CB) {
            float f[T]; ld14(s.aux + tid * 16, f);
            float fm = max14(f);
            s.fmaxs[tid] = fm;
#pragma unroll
            for (int jj = 0; jj < T; jj++) s.aux[tid * 16 + jj] = __expf(f[jj] - fm);
        }
        __syncthreads();
        if (tid < 32) {
            float ff = s.fmaxs[tid] + s.fmaxs[tid + 32];
#pragma unroll
            for (int d = 16; d; d >>= 1) ff += __shfl_xor_sync(0xFFFFFFFFu, ff, d);
            if (tid == 0) s.fsum = ff;
        }
        __syncthreads();
    }
    int warp = tid >> 5, lane = tid & 31;
    int col = 2 * warp + (lane >> 4), lg = lane & 15;
    bool ract = (lg < 14);
    float tr[T]; ld14(&s.Trs[lg * 16], tr);
    if (!fwd) {
        if (ract) s.U[0][col * 16 + lg] = (lg == col) ? 0.0f : NINF;
        __syncwarp();
        int b = 0; float vfin = NINF;
        for (int l = 0; l < CB; l++) {
            float u[T]; ld14(&s.U[b][col * 16], u);
            float a[T];
#pragma unroll
            for (int p = 0; p < T; p++) a[p] = u[p] + tr[p];
            vfin = max14(a) + s.aux[l * 16 + lg];
            if (ract) s.U[b ^ 1][col * 16 + lg] = vfin;
            __syncwarp(); b ^= 1;
        }
        if (ract) g_Cv[chunk * 224 + lg * 16 + col] = vfin;
    } else {
        if (ract) s.U[0][col * 16 + lg] = (lg == col) ? 1.0f : 0.0f;
        __syncwarp();
        int b = 0; float ffin = 0.0f, ofs = 0.0f;
        for (int l4 = 0; l4 < CB; l4 += 4) {
            {   float u[T]; ld14(&s.U[b][col * 16], u);
                float cm = fmaxf(max14(u), 1e-35f);
                float inv = __fdividef(1.0f, cm);
                ofs += __logf(cm);
                float s0 = 0.0f, s1 = 0.0f;
#pragma unroll
                for (int p = 0; p < 7; p++) s0 = fmaf(tr[p], u[p], s0);
#pragma unroll
                for (int p = 7; p < T; p++) s1 = fmaf(tr[p], u[p], s1);
                ffin = (s0 + s1) * inv * s.aux[l4 * 16 + lg];
                if (ract) s.U[b ^ 1][col * 16 + lg] = ffin;
                __syncwarp(); b ^= 1;
            }
#pragma unroll
            for (int ll = 1; ll < 4; ll++) {
                float u[T]; ld14(&s.U[b][col * 16], u);
                float s0 = 0.0f, s1 = 0.0f;
#pragma unroll
                for (int p = 0; p < 7; p++) s0 = fmaf(tr[p], u[p], s0);
#pragma unroll
                for (int p = 7; p < T; p++) s1 = fmaf(tr[p], u[p], s1);
                ffin = (s0 + s1) * s.aux[(l4 + ll) * 16 + lg];
                if (ract) s.U[b ^ 1][col * 16 + lg] = ffin;
                __syncwarp(); b ^= 1;
            }
        }
        float Cf = NINF;
        if (ract) {
            Cf = (ffin > 0.0f) ? __logf(ffin) + ofs + s.fsum : NINF;
            s.Msm[lg * 16 + col] = Cf;
        }
        __syncthreads();
        if (ract) {
            float r[T]; ld14(&s.Msm[lg * 16], r);
            float rm = max14(r);
            g_Em[chunk * 224 + lg * 16 + col] = __expf(Cf - rm);
            if (col == 0) g_m[chunk * 16 + lg] = rm;
        }
    }
}

// ================= K3: supers (smem-preloaded) + vit scan ====================
// bid 0-31: vit supers; 32-63: fwd supers; 64: vit scan (spins on g_cnt_sup)
__global__ void __launch_bounds__(224) k_sup(void) {
    struct SupS {
        alignas(16) float A[16 * 224];
        alignas(16) float m[256];
        alignas(16) float U[2][256];
        alignas(16) float Msm[256];
    };
    struct ScanS { alignas(16) float B[32 * 224 + 32]; };
    __shared__ union { SupS s; ScanS sc; } u_;
    int bid = blockIdx.x, tid = threadIdx.x;
    if (bid < 32) {
        // ---- viterbi super ----
        {   const float4* src = (const float4*)(g_Cv + bid * 3584);
            float4* dst = (float4*)u_.s.A;
            for (int i = tid; i < 896; i += 224) dst[i] = src[i]; }
        int n = tid % 14, c = tid / 14;
        u_.s.U[0][c * 16 + n] = (n == c) ? 0.0f : NINF;
        __syncthreads();
        int b = 0; float val = NINF;
        for (int k = 0; k < SCH; k++) {
            float row[T]; ld14(&u_.s.A[k * 224 + n * 16], row);
            float uc[T]; ld14(&u_.s.U[b][c * 16], uc);
            float a[T];
#pragma unroll
            for (int p = 0; p < T; p++) a[p] = row[p] + uc[p];
            val = max14(a);
            u_.s.U[b ^ 1][c * 16 + n] = val;
            __syncthreads(); b ^= 1;
        }
        if (c < 14) g_SCv[bid * 224 + n * 16 + c] = val;
        __threadfence(); __syncthreads();
        if (tid == 0) atomicAdd(&g_cnt_sup, 1);
    } else if (bid < 64) {
        // ---- forward super ----
        int g = bid - 32;
        {   const float4* src = (const float4*)(g_Em + g * 3584);
            float4* dst = (float4*)u_.s.A;
            for (int i = tid; i < 896; i += 224) dst[i] = src[i]; }
        {   const float4* src = (const float4*)(g_m + g * 256);
            float4* dst = (float4*)u_.s.m;
            for (int i = tid; i < 64; i += 224) dst[i] = src[i]; }
        int n = tid % 14, c = tid / 14;
        u_.s.U[0][c * 16 + n] = (n == c) ? 1.0f : 0.0f;
        __syncthreads();
        int b = 0; float val = 0.0f, o2 = 0.0f;
        for (int k = 0; k < SCH; k++) {
            float row[T]; ld14(&u_.s.A[k * 224 + n * 16], row);
            float uc[T]; ld14(&u_.s.U[b][c * 16], uc);
            float mk = u_.s.m[k * 16 + n];
            float s0 = 0.0f, s1 = 0.0f;
#pragma unroll
            for (int p = 0; p < 7; p++) s0 = fmaf(row[p], uc[p], s0);
#pragma unroll
            for (int p = 7; p < T; p++) s1 = fmaf(row[p], uc[p], s1);
            float tlog = mk + __logf(fmaxf(s0 + s1, 1e-38f));
            u_.s.Msm[c * 16 + n] = tlog;
            __syncthreads();
            float tc[T]; ld14(&u_.s.Msm[c * 16], tc);
            float cmax = max14(tc);
            val = __expf(tlog - cmax);
            u_.s.U[b ^ 1][c * 16 + n] = val;
            o2 += cmax;
            __syncthreads(); b ^= 1;
        }
        float Sl = (val > 0.0f) ? __logf(val) + o2 : NINF;
        u_.s.Msm[n * 16 + c] = Sl;
        __syncthreads();
        if (c < 14) {
            float r[T]; ld14(&u_.s.Msm[n * 16], r);
            float rm = max14(r);
            g_SEm[g * 224 + n * 16 + c] = __expf(Sl - rm);
            if (c == 0) g_Sm[g * 16 + n] = rm;
        }
    } else {
        // ---- vit scan ----
        if (tid == 0) { while (atomicAdd(&g_cnt_sup, 0) < 32) __nanosleep(64); }
        __syncthreads(); __threadfence();
        {   const float4* src = (const float4*)g_SCv;
            float4* dst = (float4*)u_.sc.B;
            for (int i = tid; i < 1792; i += 224) dst[i] = __ldcg(src + i); }
        __syncthreads();
        if (tid < 16) {
            const unsigned M16 = 0xFFFFu;
            int ln = tid;
            float v = (ln == START_TAG) ? 0.0f : NEGV;
            for (int i = 0; i < SUPER; i++) {
                g_vsuper[i * 16 + ln] = (ln < T) ? v : NEGV;
                float row[T]; ld14(&u_.sc.B[i * 224 + ln * 16], row);
                float nv = -3e38f;
#pragma unroll
                for (int p = 0; p < T; p++) {
                    float vp = __shfl_sync(M16, v, p, 16);
                    nv = fmaxf(nv, row[p] + vp);
                }
                v = (ln < T) ? nv : NEGV;
            }
        }
    }
}

// ================= K4: tail (quartered) + fwd scan block (513 x 256) =========
__global__ void __launch_bounds__(256) k_tail(const float* __restrict__ trans,
                                              float* __restrict__ out) {
    struct TailS {
        alignas(16) float raw[CB * 16];
        alignas(16) float fix[15 * 224 + 4];
        alignas(16) float vs[16];
        alignas(16) float term[16];
        alignas(16) unsigned char bp[CB * T];
        alignas(16) unsigned char Fs[CHUNKS * T];
        alignas(16) unsigned char Q[4][16];
        alignas(16) unsigned char comp[16 * T];
        int sgrp[17];
        int role;
    };
    struct FscanS {
        alignas(16) float B[32 * 224 + 32];
        alignas(16) float m[SUPER * 16 + 16];
        alignas(16) float gold[512];
    };
    __shared__ union { TailS t; FscanS f; } u_;
    int bid = blockIdx.x, tid = threadIdx.x;

    if (bid == 512) {
        // ---- forward scan + nll (hides under the 512 tail blocks) ----
        if (tid == 0) g_cnt_sup = 0;                 // reset for next replay
        {   const float4* src = (const float4*)g_SEm;
            float4* dst = (float4*)u_.f.B;
            for (int i = tid; i < 1792; i += 256) dst[i] = src[i]; }
        {   const float4* src = (const float4*)g_Sm;
            float4* dst = (float4*)u_.f.m;
            for (int i = tid; i < 128; i += 256) dst[i] = src[i]; }
        {   const float4* src = (const float4*)g_goldpart;
            float4* dst = (float4*)u_.f.gold;
            for (int i = tid; i < 128; i += 256) dst[i] = src[i]; }
        __syncthreads();
        if (tid < 16) {
            const unsigned M16 = 0xFFFFu;
            int ln = tid;
            float u = (ln == START_TAG) ? 1.0f : 0.0f;
            float O = 0.0f;
            for (int i = 0; i < SUPER; i++) {
                float row[T]; float mk;
                if (ln < T) { ld14(&u_.f.B[i * 224 + ln * 16], row);
                              mk = u_.f.m[i * 16 + ln]; }
                else {
#pragma unroll
                    for (int p = 0; p < T; p++) row[p] = 0.0f;
                    mk = -3e38f;
                }
                float w = 0.0f;
#pragma unroll
                for (int p = 0; p < T; p++) {
                    float up = __shfl_sync(M16, u, p, 16);
                    w = fmaf(row[p], up, w);
                }
                float t2 = mk + __logf(fmaxf(w, 1e-38f));
                float M = t2;
#pragma unroll
                for (int d = 8; d; d >>= 1) M = fmaxf(M, __shfl_xor_sync(M16, M, d, 16));
                u = __expf(t2 - M);
                O += M;
            }
            float val = (ln < T) ? (((u > 0.0f) ? __logf(u) : NINF) + O +
                                    trans[STOP_TAG * T + ln])
                                 : -3e38f;
            float M2 = val;
#pragma unroll
            for (int d = 8; d; d >>= 1) M2 = fmaxf(M2, __shfl_xor_sync(M16, M2, d, 16));
            float e = __expf(val - M2);
#pragma unroll
            for (int d = 8; d; d >>= 1) e += __shfl_xor_sync(M16, e, d, 16);
            float fwd_score = M2 + __logf(e);
            float gp = 0.0f;
            for (int jj = ln; jj < 512; jj += 16) gp += u_.f.gold[jj];
#pragma unroll
            for (int d = 8; d; d >>= 1) gp += __shfl_xor_sync(M16, gp, d, 16);
            if (ln == 0) out[0] = fwd_score - gp;    // nll
        }
        return;
    }

    // ---- tail role ----
    int chunk = bid;
    int sup = chunk >> 4, base = sup << 4, r = chunk - base;
    {   const float4* src = (const float4*)(g_featsP + chunk * CB * 16);
        float4* dst = (float4*)u_.t.raw;
        for (int i = tid; i < CB * 4; i += 256) dst[i] = src[i]; }
    if (r > 0) {
        const float4* src = (const float4*)(g_Cv + base * 224);
        float4* dst = (float4*)u_.t.fix;
        for (int i = tid; i < r * 56; i += 256) dst[i] = src[i];
    }
    if (tid < 4) ((float4*)u_.t.vs)[tid] = ((const float4*)(g_vsuper + sup * 16))[tid];
    __syncthreads();
    if (tid < T) {
        int ln = tid;
        float v = u_.t.vs[ln];
        for (int k = 0; k < r; k++) {
            float row[T]; ld14(&u_.t.fix[k * 224 + ln * 16], row);
            float fvall[T];
#pragma unroll
            for (int p = 0; p < T; p++) fvall[p] = __shfl_sync(0x3FFFu, v, p);
            float nv = NINF;
#pragma unroll
            for (int p = 0; p < T; p++) nv = fmaxf(nv, row[p] + fvall[p]);
            v = nv;
        }
        float tr[T];
#pragma unroll
        for (int p = 0; p < T; p++) tr[p] = trans[ln * T + p];
        float fv = v;
        for (int l = 0; l < CB; l++) {
            float fvall[T];
#pragma unroll
            for (int p = 0; p < T; p++) fvall[p] = __shfl_sync(0x3FFFu, fv, p);
            float a[T];
#pragma unroll
            for (int p = 0; p < T; p++) a[p] = fvall[p] + tr[p];
            float best = max14(a);                    // critical path: FMNMX only
            fv = best + u_.t.raw[l * 16 + ln];
            u_.t.bp[l * T + ln] = (unsigned char)argfirst14(a, best);  // off-path
        }
        if (chunk == CHUNKS - 1) u_.t.term[ln] = fv + trans[STOP_TAG * T + ln];
    }
    __syncthreads();
    // quarter backtrace maps (4 x 14 threads, 16 steps each)
    if (tid < 56) {
        int q = tid / 14, x = tid % 14;
        int t = x;
        for (int l = q * 16 + 15; l >= q * 16; l--) t = u_.t.bp[l * T + t];
        u_.t.Q[q][x] = (unsigned char)t;
    }
    __syncthreads();
    if (tid < T) {
        int x = tid;
        g_F[chunk * T + x] = u_.t.Q[0][u_.t.Q[1][u_.t.Q[2][u_.t.Q[3][x]]]];
    }
    if (chunk == CHUNKS - 1 && tid == 0) {
        float a2[T];
#pragma unroll
        for (int p = 0; p < T; p++) a2[p] = u_.t.term[p];
        float best = max14(a2);
        g_best_last = argfirst14(a2, best);
        out[1] = best;                                 // path_score
    }
    __threadfence(); __syncthreads();
    if (tid == 0) {
        int old = atomicAdd(&g_cnt_bp, 1);
        u_.t.role = (old == CHUNKS - 1);
    }
    __syncthreads();
    if (u_.t.role) {
        // ---- carry (last-done block): 16 groups of 32 chunks ----
        __threadfence();
        {   const int4* src = (const int4*)g_F;
            int4* dst = (int4*)u_.t.Fs;
            for (int i = tid; i < (CHUNKS * T) / 16; i += 256) dst[i] = __ldcg(src + i); }
        __syncthreads();
        if (tid < 16 * T) {
            int g = tid / T, x = tid % T;
            int t = x;
            for (int l = g * 32 + 31; l >= g * 32; l--) t = u_.t.Fs[l * T + t];
            u_.t.comp[g * T + x] = (unsigned char)t;
        }
        __syncthreads();
        if (tid == 0) {
            int sgv = g_best_last;
            u_.t.sgrp[16] = sgv;
            for (int g = 15; g >= 0; g--) { sgv = u_.t.comp[g * T + sgv]; u_.t.sgrp[g] = sgv; }
        }
        __syncthreads();
        if (tid < 16) {
            int g = tid;
            int t = u_.t.sgrp[g + 1];
            for (int l = g * 32 + 31; l >= g * 32; l--) {
                g_carry[l] = t;
                t = u_.t.Fs[l * T + t];
            }
        }
        __threadfence(); __syncthreads();
        if (tid == 0) atomicExch(&g_flag, 1);
    } else {
        if (tid == 0) { while (atomicAdd(&g_flag, 0) == 0) __nanosleep(128); }
        __syncthreads();
    }
    __threadfence();
    // ---- emit: 4 parallel 16-step quarter walks ----
    if (tid < 4) {
        int q = tid;
        int s3 = g_carry[chunk];
        int s2 = u_.t.Q[3][s3];
        int s1 = u_.t.Q[2][s2];
        int s0 = u_.t.Q[1][s1];
        int st = (q == 3) ? s3 : (q == 2) ? s2 : (q == 1) ? s1 : s0;
        for (int l = q * 16 + 15; l >= q * 16; l--) {
            out[2 + chunk * CB + l] = (float)st;
            st = u_.t.bp[l * T + st];
        }
    }
}

// ---------------- launch -----------------------------------------------------
extern "C" void kernel_launch(void* const* d_in, const int* in_sizes, int n_in,
                              void* d_out, int out_size) {
    const int*   sent  = (const int*)d_in[0];
    const int*   tags  = (const int*)d_in[1];
    const float* emb   = (const float*)d_in[2];
    const float* W     = (const float*)d_in[3];
    const float* trans = (const float*)d_in[4];
    float* out = (float*)d_out;
    (void)in_sizes; (void)n_in; (void)out_size;

    k_feats<<<512, 128>>>(sent, tags, emb, W, trans);
    k_chunks<<<2 * CHUNKS, 224>>>(trans);
    k_sup<<<65, 224>>>();
    k_tail<<<CHUNKS + 1, 256>>>(trans, out);
}